// round 12
// baseline (speedup 1.0000x reference)
#include <cuda_runtime.h>
#include <mma.h>
#include <cstdint>

using namespace nvcuda;

#define MAXN 50176
#define MAXE 800000
#define SCAN_BLK 256

// ---------------- scratch (device globals; no allocation allowed) -----------
__device__ int   g_is64;                           // edge dtype flag
__device__ int   g_total;                          // atomic scan cursor
__device__ int   g_src[MAXE];                      // decoded src ids (int32)
__device__ int   g_dst[MAXE];                      // decoded dst ids (int32)
__device__ int   g_cnt[MAXN + 1];                  // per-node degree
__device__ int   g_rowptr[MAXN + 1];               // CSR segment starts
__device__ int   g_cur[MAXN + 1];                  // fill cursors
__device__ int   g_csr[MAXE];                      // src ids grouped by dst
__device__ float g_t2[(size_t)MAXN * 64];          // h @ W2l (padded)
__device__ float g_opart[(size_t)MAXN * 64];       // h @ W2r (padded)

// ---------------- detect dtype + zero counters (fused) ------------------------
__global__ void detect_zero_kernel(const int* __restrict__ w, int N, int nblk) {
    if ((int)blockIdx.x == nblk) {
        __shared__ int nonzero;
        if (threadIdx.x == 0) nonzero = 0;
        __syncthreads();
        int nz = 0;
        for (int i = threadIdx.x; i < 1024; i += 256)
            if (w[2 * i + 1] != 0) nz = 1;
        if (nz) nonzero = 1;          // benign race
        __syncthreads();
        if (threadIdx.x == 0) g_is64 = (nonzero == 0) ? 1 : 0;
        return;
    }
    if (blockIdx.x == 0 && threadIdx.x == 0) g_total = 0;
    int i = blockIdx.x * blockDim.x + threadIdx.x;
    if (i <= N) g_cnt[i] = 0;
}

// ---------------- decode + histogram ------------------------------------------
__global__ void convert_hist_kernel(const int* __restrict__ w, int E, int N) {
    int e = blockIdx.x * blockDim.x + threadIdx.x;
    if (e >= E) return;
    int s, d;
    if (g_is64) {
        s = w[2 * e];
        d = w[2 * (E + e)];
    } else {
        s = w[e];
        d = w[E + e];
    }
    s = min(max(s, 0), N - 1);        // clamp: never trap on bad data
    d = min(max(d, 0), N - 1);
    g_src[e] = s;
    g_dst[e] = d;
    atomicAdd(&g_cnt[d], 1);
}

// ---------------- single-pass scan: block scan + atomic global offset ----------
__device__ __forceinline__ int block_incl_scan(int v, int* wsum) {
    int lane = threadIdx.x & 31;
    int w = threadIdx.x >> 5;
    int x = v;
#pragma unroll
    for (int o = 1; o < 32; o <<= 1) {
        int y = __shfl_up_sync(0xffffffffu, x, o);
        if (lane >= o) x += y;
    }
    if (lane == 31) wsum[w] = x;
    __syncthreads();
    if (w == 0 && lane < 8) {
        int s = wsum[lane];
#pragma unroll
        for (int o = 1; o < 8; o <<= 1) {
            int y = __shfl_up_sync(0xffu, s, o);
            if (lane >= o) s += y;
        }
        wsum[lane] = s;
    }
    __syncthreads();
    return x + (w > 0 ? wsum[w - 1] : 0);
}

// Segments need not be in node order (degree comes from g_cnt), so each block
// grabs its offset atomically — no second pass.
__global__ void __launch_bounds__(SCAN_BLK) scan_atomic_kernel(int N) {
    __shared__ int wsum[8];
    __shared__ int blockoff;
    int i = blockIdx.x * SCAN_BLK + threadIdx.x;
    int v = (i < N) ? g_cnt[i] : 0;
    int incl = block_incl_scan(v, wsum);
    if (threadIdx.x == SCAN_BLK - 1) blockoff = atomicAdd(&g_total, incl);
    __syncthreads();
    if (i < N) {
        int r = blockoff + incl - v;
        g_rowptr[i] = r;
        g_cur[i] = r;
    }
}

__global__ void fill_kernel(int E) {
    int e = blockIdx.x * blockDim.x + threadIdx.x;
    if (e >= E) return;
    int pos = atomicAdd(&g_cur[g_dst[e]], 1);
    g_csr[pos] = g_src[e];
}

// ---------------- WMMA helpers -------------------------------------------------
using FragA = wmma::fragment<wmma::matrix_a, 16, 16, 8, wmma::precision::tf32, wmma::row_major>;
using FragB = wmma::fragment<wmma::matrix_b, 16, 16, 8, wmma::precision::tf32, wmma::row_major>;
using FragC = wmma::fragment<wmma::accumulator, 16, 16, 8, float>;

__device__ __forceinline__ void cvt_tf32(FragA& f) {
#pragma unroll
    for (int i = 0; i < f.num_elements; i++) f.x[i] = wmma::__float_to_tf32(f.x[i]);
}
__device__ __forceinline__ void cvt_tf32(FragB& f) {
#pragma unroll
    for (int i = 0; i < f.num_elements; i++) f.x[i] = wmma::__float_to_tf32(f.x[i]);
}

// ---------------- mega kernel: gather + layer-1 GEMM + both layer-2 transforms -
// Phase 0: As[n,:] = mean of x over in-neighbors (warp-per-node, MLP=4)
// Phase 1: h = relu(As @ W1l + x @ W1r + b1) -> Hs (smem only)
// Phase 2: t2 = Hs @ W2l -> g_t2 ; o_part = Hs @ W2r -> g_opart
__global__ void __launch_bounds__(256, 2)
gemm1_mega(const float* __restrict__ x, const float* __restrict__ W1l,
           const float* __restrict__ W1r, const float* __restrict__ b1,
           const float* __restrict__ W2l, const float* __restrict__ W2r, int N) {
    constexpr int ASTR = 132;    // As/Hs row stride (128 cols)
    constexpr int WSTR = 132;    // Ws row stride (128 cols)
    constexpr int W2STR = 68;    // W2s/W3s row stride (64 cols)

    __shared__ __align__(16) float smem[10624];   // 42496 B
    float* As  = smem;
    float* Hs  = smem;
    float* Ws  = smem + 64 * ASTR;           // phase 1 weights [16 x 132]
    float* W2s = smem + 64 * ASTR;           // phase 2: [16 x 68]
    float* W3s = W2s + 16 * W2STR;           // phase 2: [16 x 68]

    const int tid  = threadIdx.x;
    const int wid  = tid >> 5;
    const int lane = tid & 31;
    const int base = blockIdx.x * 64;

    // ---- phase 0: gather-mean of x into As (4 loads in flight) ----
    for (int n = wid; n < 64; n += 8) {
        int node = base + n;
        float4 a0 = make_float4(0.f, 0.f, 0.f, 0.f);
        float4 a1 = make_float4(0.f, 0.f, 0.f, 0.f);
        float4 a2 = make_float4(0.f, 0.f, 0.f, 0.f);
        float4 a3 = make_float4(0.f, 0.f, 0.f, 0.f);
        float rd = 0.f;
        if (node < N) {
            int beg = g_rowptr[node];
            int deg = g_cnt[node];
            int end = beg + deg;
            int i = beg;
            for (; i + 3 < end; i += 4) {
                int s0 = g_csr[i];
                int s1 = g_csr[i + 1];
                int s2 = g_csr[i + 2];
                int s3 = g_csr[i + 3];
                float4 v0 = reinterpret_cast<const float4*>(x + (size_t)s0 * 128)[lane];
                float4 v1 = reinterpret_cast<const float4*>(x + (size_t)s1 * 128)[lane];
                float4 v2 = reinterpret_cast<const float4*>(x + (size_t)s2 * 128)[lane];
                float4 v3 = reinterpret_cast<const float4*>(x + (size_t)s3 * 128)[lane];
                a0.x += v0.x; a0.y += v0.y; a0.z += v0.z; a0.w += v0.w;
                a1.x += v1.x; a1.y += v1.y; a1.z += v1.z; a1.w += v1.w;
                a2.x += v2.x; a2.y += v2.y; a2.z += v2.z; a2.w += v2.w;
                a3.x += v3.x; a3.y += v3.y; a3.z += v3.z; a3.w += v3.w;
            }
            for (; i < end; i++) {
                int s0 = g_csr[i];
                float4 v0 = reinterpret_cast<const float4*>(x + (size_t)s0 * 128)[lane];
                a0.x += v0.x; a0.y += v0.y; a0.z += v0.z; a0.w += v0.w;
            }
            rd = (deg > 0) ? (1.0f / (float)deg) : 0.0f;
        }
        float4 r;
        r.x = (a0.x + a1.x + a2.x + a3.x) * rd;
        r.y = (a0.y + a1.y + a2.y + a3.y) * rd;
        r.z = (a0.z + a1.z + a2.z + a3.z) * rd;
        r.w = (a0.w + a1.w + a2.w + a3.w) * rd;
        *reinterpret_cast<float4*>(As + n * ASTR + lane * 4) = r;
    }
    __syncthreads();

    // ---- phase 1 GEMM: mean@W1l then x@W1r ----
    const int wr = wid >> 1;           // 4 row chunks of 16 nodes
    const int wc = wid & 1;            // 2 col halves of 64

    FragC acc[4];
#pragma unroll
    for (int j = 0; j < 4; j++) wmma::fill_fragment(acc[j], 0.0f);

#pragma unroll
    for (int s = 0; s < 2; s++) {
        const float* Wsrc = s ? W1r : W1l;
        if (s == 1) {
            __syncthreads();
            for (int i = tid; i < 2048; i += 256) {
                int r = i >> 5, c4 = i & 31;
                int node = base + r;
                float4 v = make_float4(0.f, 0.f, 0.f, 0.f);
                if (node < N)
                    v = reinterpret_cast<const float4*>(x + (size_t)node * 128)[c4];
                *reinterpret_cast<float4*>(As + r * ASTR + c4 * 4) = v;
            }
            __syncthreads();
        }
        for (int ck = 0; ck < 8; ck++) {
            __syncthreads();
            for (int i = tid; i < 512; i += 256) {
                int row = i >> 5, c4 = i & 31;
                *reinterpret_cast<float4*>(Ws + row * WSTR + c4 * 4) =
                    reinterpret_cast<const float4*>(Wsrc)[(ck * 16 + row) * 32 + c4];
            }
            __syncthreads();
#pragma unroll
            for (int k0 = 0; k0 < 16; k0 += 8) {
                FragA af;
                wmma::load_matrix_sync(af, As + wr * 16 * ASTR + ck * 16 + k0, ASTR);
                cvt_tf32(af);
#pragma unroll
                for (int j = 0; j < 4; j++) {
                    FragB bf;
                    wmma::load_matrix_sync(bf, Ws + k0 * WSTR + wc * 64 + j * 16, WSTR);
                    cvt_tf32(bf);
                    wmma::mma_sync(acc[j], af, bf, acc[j]);
                }
            }
        }
    }

    // ---- phase 1 epilogue: acc -> Hs, bias+relu (smem only) ----
    __syncthreads();
#pragma unroll
    for (int j = 0; j < 4; j++)
        wmma::store_matrix_sync(Hs + wr * 16 * ASTR + wc * 64 + j * 16, acc[j],
                                ASTR, wmma::mem_row_major);
    __syncthreads();
    for (int i = tid; i < 2048; i += 256) {
        int r = i >> 5, c4 = i & 31;
        float4 v = *reinterpret_cast<float4*>(Hs + r * ASTR + c4 * 4);
        float4 bb = reinterpret_cast<const float4*>(b1)[c4];
        v.x = fmaxf(v.x + bb.x, 0.f);
        v.y = fmaxf(v.y + bb.y, 0.f);
        v.z = fmaxf(v.z + bb.z, 0.f);
        v.w = fmaxf(v.w + bb.w, 0.f);
        *reinterpret_cast<float4*>(Hs + r * ASTR + c4 * 4) = v;
    }

    // ---- phase 2: t2 = Hs @ W2l ; o_part = Hs @ W2r (shared Hs reads) ----
    const int r2 = wid >> 1;
    const int cb = (wid & 1) * 2;
    FragC a2f[2], a3f[2];
    wmma::fill_fragment(a2f[0], 0.0f);
    wmma::fill_fragment(a2f[1], 0.0f);
    wmma::fill_fragment(a3f[0], 0.0f);
    wmma::fill_fragment(a3f[1], 0.0f);

    for (int ck = 0; ck < 8; ck++) {
        __syncthreads();
        {
            int row = tid >> 4, c4 = tid & 15;
            *reinterpret_cast<float4*>(W2s + row * W2STR + c4 * 4) =
                reinterpret_cast<const float4*>(W2l)[(ck * 16 + row) * 16 + c4];
            *reinterpret_cast<float4*>(W3s + row * W2STR + c4 * 4) =
                reinterpret_cast<const float4*>(W2r)[(ck * 16 + row) * 16 + c4];
        }
        __syncthreads();
#pragma unroll
        for (int k0 = 0; k0 < 16; k0 += 8) {
            FragA af;
            wmma::load_matrix_sync(af, Hs + r2 * 16 * ASTR + ck * 16 + k0, ASTR);
            cvt_tf32(af);
#pragma unroll
            for (int j = 0; j < 2; j++) {
                FragB bf;
                wmma::load_matrix_sync(bf, W2s + k0 * W2STR + (cb + j) * 16, W2STR);
                cvt_tf32(bf);
                wmma::mma_sync(a2f[j], af, bf, a2f[j]);
                FragB bf2;
                wmma::load_matrix_sync(bf2, W3s + k0 * W2STR + (cb + j) * 16, W2STR);
                cvt_tf32(bf2);
                wmma::mma_sync(a3f[j], af, bf2, a3f[j]);
            }
        }
    }
#pragma unroll
    for (int j = 0; j < 2; j++) {
        wmma::store_matrix_sync(g_t2 + (size_t)(base + r2 * 16) * 64 + (cb + j) * 16,
                                a2f[j], 64, wmma::mem_row_major);   // padded
        wmma::store_matrix_sync(g_opart + (size_t)(base + r2 * 16) * 64 + (cb + j) * 16,
                                a3f[j], 64, wmma::mem_row_major);   // padded
    }
}

// ---------------- final kernel: out = mean-gather(t2) + o_part + b2 ------------
__global__ void __launch_bounds__(256)
out_gather_kernel(const float* __restrict__ b2, float* __restrict__ outp, int N) {
    int node = (int)(((size_t)blockIdx.x * blockDim.x + threadIdx.x) >> 5);
    int lane = threadIdx.x & 31;
    if (node >= N) return;
    int beg = g_rowptr[node];
    int deg = g_cnt[node];
    int end = beg + deg;
    float2 a0 = make_float2(0.f, 0.f);
    float2 a1 = make_float2(0.f, 0.f);
    float2 a2 = make_float2(0.f, 0.f);
    float2 a3 = make_float2(0.f, 0.f);
    int i = beg;
    for (; i + 3 < end; i += 4) {
        int s0 = g_csr[i];
        int s1 = g_csr[i + 1];
        int s2 = g_csr[i + 2];
        int s3 = g_csr[i + 3];
        float2 v0 = reinterpret_cast<const float2*>(g_t2 + (size_t)s0 * 64)[lane];
        float2 v1 = reinterpret_cast<const float2*>(g_t2 + (size_t)s1 * 64)[lane];
        float2 v2 = reinterpret_cast<const float2*>(g_t2 + (size_t)s2 * 64)[lane];
        float2 v3 = reinterpret_cast<const float2*>(g_t2 + (size_t)s3 * 64)[lane];
        a0.x += v0.x; a0.y += v0.y;
        a1.x += v1.x; a1.y += v1.y;
        a2.x += v2.x; a2.y += v2.y;
        a3.x += v3.x; a3.y += v3.y;
    }
    for (; i < end; i++) {
        int s0 = g_csr[i];
        float2 v0 = reinterpret_cast<const float2*>(g_t2 + (size_t)s0 * 64)[lane];
        a0.x += v0.x; a0.y += v0.y;
    }
    float rd = (deg > 0) ? (1.0f / (float)deg) : 0.0f;
    float2 op = reinterpret_cast<const float2*>(g_opart + (size_t)node * 64)[lane];
    float2 bb = reinterpret_cast<const float2*>(b2)[lane];
    float2 r;
    r.x = (a0.x + a1.x + a2.x + a3.x) * rd + op.x + bb.x;
    r.y = (a0.y + a1.y + a2.y + a3.y) * rd + op.y + bb.y;
    reinterpret_cast<float2*>(outp + (size_t)node * 64)[lane] = r;
}

// ---------------- launch -------------------------------------------------------
extern "C" void kernel_launch(void* const* d_in, const int* in_sizes, int n_in,
                              void* d_out, int out_size) {
    const float* x       = (const float*)d_in[0];
    const int*   ei_w    = (const int*)d_in[1];
    const float* W1l     = (const float*)d_in[2];
    const float* b1      = (const float*)d_in[3];
    const float* W1r     = (const float*)d_in[4];
    const float* W2l     = (const float*)d_in[5];
    const float* b2      = (const float*)d_in[6];
    const float* W2r     = (const float*)d_in[7];
    float* out = (float*)d_out;

    int N = in_sizes[0] / 128;
    int E = in_sizes[1] / 2;
    int nblk = (N + SCAN_BLK - 1) / SCAN_BLK;

    // --- decode + CSR build (4 launches) ---
    detect_zero_kernel<<<nblk + 1, 256>>>(ei_w, N, nblk);
    convert_hist_kernel<<<(E + 255) / 256, 256>>>(ei_w, E, N);
    scan_atomic_kernel<<<nblk, SCAN_BLK>>>(N);
    fill_kernel<<<(E + 255) / 256, 256>>>(E);

    // --- layer 1 gather + dual GEMM + both layer-2 transforms ---
    gemm1_mega<<<(N + 63) / 64, 256>>>(x, W1l, W1r, b1, W2l, W2r, N);

    // --- final: gather t2-mean + add o_part + bias ---
    {
        size_t threads = (size_t)N * 32;
        out_gather_kernel<<<(int)((threads + 255) / 256), 256>>>(b2, out, N);
    }
}

// round 13
// speedup vs baseline: 1.1691x; 1.1691x over previous
#include <cuda_runtime.h>
#include <mma.h>
#include <cstdint>

using namespace nvcuda;

#define MAXN 50176
#define MAXE 800000
#define SCAN_BLK 256

// ---------------- scratch (device globals; no allocation allowed) -----------
__device__ int   g_is64;                           // edge dtype flag
__device__ int   g_total;                          // atomic scan cursor
__device__ int   g_src[MAXE];                      // decoded src ids (int32)
__device__ int   g_dst[MAXE];                      // decoded dst ids (int32)
__device__ int   g_cnt[MAXN + 1];                  // per-node degree
__device__ int   g_rowptr[MAXN + 1];               // CSR segment starts
__device__ int   g_cur[MAXN + 1];                  // fill cursors
__device__ int   g_csr[MAXE];                      // src ids grouped by dst
__device__ float g_t2[(size_t)MAXN * 64];          // h @ W2l (padded)
__device__ float g_opart[(size_t)MAXN * 64];       // h @ W2r (padded)

// ---------------- detect dtype + zero counters (fused) ------------------------
__global__ void detect_zero_kernel(const int* __restrict__ w, int N, int nblk) {
    if ((int)blockIdx.x == nblk) {
        __shared__ int nonzero;
        if (threadIdx.x == 0) nonzero = 0;
        __syncthreads();
        int nz = 0;
        for (int i = threadIdx.x; i < 1024; i += 256)
            if (w[2 * i + 1] != 0) nz = 1;
        if (nz) nonzero = 1;          // benign race
        __syncthreads();
        if (threadIdx.x == 0) g_is64 = (nonzero == 0) ? 1 : 0;
        return;
    }
    if (blockIdx.x == 0 && threadIdx.x == 0) g_total = 0;
    int i = blockIdx.x * blockDim.x + threadIdx.x;
    if (i <= N) g_cnt[i] = 0;
}

// ---------------- decode + histogram ------------------------------------------
__global__ void convert_hist_kernel(const int* __restrict__ w, int E, int N) {
    int e = blockIdx.x * blockDim.x + threadIdx.x;
    if (e >= E) return;
    int s, d;
    if (g_is64) {
        s = w[2 * e];
        d = w[2 * (E + e)];
    } else {
        s = w[e];
        d = w[E + e];
    }
    s = min(max(s, 0), N - 1);        // clamp: never trap on bad data
    d = min(max(d, 0), N - 1);
    g_src[e] = s;
    g_dst[e] = d;
    atomicAdd(&g_cnt[d], 1);
}

// ---------------- single-pass scan: block scan + atomic global offset ----------
__device__ __forceinline__ int block_incl_scan(int v, int* wsum) {
    int lane = threadIdx.x & 31;
    int w = threadIdx.x >> 5;
    int x = v;
#pragma unroll
    for (int o = 1; o < 32; o <<= 1) {
        int y = __shfl_up_sync(0xffffffffu, x, o);
        if (lane >= o) x += y;
    }
    if (lane == 31) wsum[w] = x;
    __syncthreads();
    if (w == 0 && lane < 8) {
        int s = wsum[lane];
#pragma unroll
        for (int o = 1; o < 8; o <<= 1) {
            int y = __shfl_up_sync(0xffu, s, o);
            if (lane >= o) s += y;
        }
        wsum[lane] = s;
    }
    __syncthreads();
    return x + (w > 0 ? wsum[w - 1] : 0);
}

// Segments need not be in node order (degree comes from g_cnt), so each block
// grabs its offset atomically — no second pass.
__global__ void __launch_bounds__(SCAN_BLK) scan_atomic_kernel(int N) {
    __shared__ int wsum[8];
    __shared__ int blockoff;
    int i = blockIdx.x * SCAN_BLK + threadIdx.x;
    int v = (i < N) ? g_cnt[i] : 0;
    int incl = block_incl_scan(v, wsum);
    if (threadIdx.x == SCAN_BLK - 1) blockoff = atomicAdd(&g_total, incl);
    __syncthreads();
    if (i < N) {
        int r = blockoff + incl - v;
        g_rowptr[i] = r;
        g_cur[i] = r;
    }
}

__global__ void fill_kernel(int E) {
    int e = blockIdx.x * blockDim.x + threadIdx.x;
    if (e >= E) return;
    int pos = atomicAdd(&g_cur[g_dst[e]], 1);
    g_csr[pos] = g_src[e];
}

// ---------------- WMMA helpers -------------------------------------------------
using FragA = wmma::fragment<wmma::matrix_a, 16, 16, 8, wmma::precision::tf32, wmma::row_major>;
using FragB = wmma::fragment<wmma::matrix_b, 16, 16, 8, wmma::precision::tf32, wmma::row_major>;
using FragC = wmma::fragment<wmma::accumulator, 16, 16, 8, float>;

__device__ __forceinline__ void cvt_tf32(FragA& f) {
#pragma unroll
    for (int i = 0; i < f.num_elements; i++) f.x[i] = wmma::__float_to_tf32(f.x[i]);
}
__device__ __forceinline__ void cvt_tf32(FragB& f) {
#pragma unroll
    for (int i = 0; i < f.num_elements; i++) f.x[i] = wmma::__float_to_tf32(f.x[i]);
}

// ---------------- mega kernel: gather + layer-1 GEMM + both layer-2 transforms -
// (R11 form: MLP=2 gather, no occupancy clause — that combo was the fastest)
__global__ void __launch_bounds__(256)
gemm1_mega(const float* __restrict__ x, const float* __restrict__ W1l,
           const float* __restrict__ W1r, const float* __restrict__ b1,
           const float* __restrict__ W2l, const float* __restrict__ W2r, int N) {
    constexpr int ASTR = 132;    // As/Hs row stride (128 cols)
    constexpr int WSTR = 132;    // Ws row stride (128 cols)
    constexpr int W2STR = 68;    // W2s/W3s row stride (64 cols)

    __shared__ __align__(16) float smem[10624];   // 42496 B
    float* As  = smem;
    float* Hs  = smem;
    float* Ws  = smem + 64 * ASTR;           // phase 1 weights [16 x 132]
    float* W2s = smem + 64 * ASTR;           // phase 2: [16 x 68]
    float* W3s = W2s + 16 * W2STR;           // phase 2: [16 x 68]

    const int tid  = threadIdx.x;
    const int wid  = tid >> 5;
    const int lane = tid & 31;
    const int base = blockIdx.x * 64;

    // ---- phase 0: gather-mean of x into As ----
    for (int n = wid; n < 64; n += 8) {
        int node = base + n;
        float4 a0 = make_float4(0.f, 0.f, 0.f, 0.f);
        float4 a1 = make_float4(0.f, 0.f, 0.f, 0.f);
        float rd = 0.f;
        if (node < N) {
            int beg = g_rowptr[node];
            int deg = g_cnt[node];
            int end = beg + deg;
            int i = beg;
            for (; i + 1 < end; i += 2) {
                int s0 = g_csr[i];
                int s1 = g_csr[i + 1];
                float4 v0 = reinterpret_cast<const float4*>(x + (size_t)s0 * 128)[lane];
                float4 v1 = reinterpret_cast<const float4*>(x + (size_t)s1 * 128)[lane];
                a0.x += v0.x; a0.y += v0.y; a0.z += v0.z; a0.w += v0.w;
                a1.x += v1.x; a1.y += v1.y; a1.z += v1.z; a1.w += v1.w;
            }
            if (i < end) {
                int s0 = g_csr[i];
                float4 v0 = reinterpret_cast<const float4*>(x + (size_t)s0 * 128)[lane];
                a0.x += v0.x; a0.y += v0.y; a0.z += v0.z; a0.w += v0.w;
            }
            rd = (deg > 0) ? (1.0f / (float)deg) : 0.0f;
        }
        float4 r;
        r.x = (a0.x + a1.x) * rd;
        r.y = (a0.y + a1.y) * rd;
        r.z = (a0.z + a1.z) * rd;
        r.w = (a0.w + a1.w) * rd;
        *reinterpret_cast<float4*>(As + n * ASTR + lane * 4) = r;
    }
    __syncthreads();

    // ---- phase 1 GEMM: mean@W1l then x@W1r ----
    const int wr = wid >> 1;           // 4 row chunks of 16 nodes
    const int wc = wid & 1;            // 2 col halves of 64

    FragC acc[4];
#pragma unroll
    for (int j = 0; j < 4; j++) wmma::fill_fragment(acc[j], 0.0f);

#pragma unroll
    for (int s = 0; s < 2; s++) {
        const float* Wsrc = s ? W1r : W1l;
        if (s == 1) {
            __syncthreads();
            for (int i = tid; i < 2048; i += 256) {
                int r = i >> 5, c4 = i & 31;
                int node = base + r;
                float4 v = make_float4(0.f, 0.f, 0.f, 0.f);
                if (node < N)
                    v = reinterpret_cast<const float4*>(x + (size_t)node * 128)[c4];
                *reinterpret_cast<float4*>(As + r * ASTR + c4 * 4) = v;
            }
            __syncthreads();
        }
        for (int ck = 0; ck < 8; ck++) {
            __syncthreads();
            for (int i = tid; i < 512; i += 256) {
                int row = i >> 5, c4 = i & 31;
                *reinterpret_cast<float4*>(Ws + row * WSTR + c4 * 4) =
                    reinterpret_cast<const float4*>(Wsrc)[(ck * 16 + row) * 32 + c4];
            }
            __syncthreads();
#pragma unroll
            for (int k0 = 0; k0 < 16; k0 += 8) {
                FragA af;
                wmma::load_matrix_sync(af, As + wr * 16 * ASTR + ck * 16 + k0, ASTR);
                cvt_tf32(af);
#pragma unroll
                for (int j = 0; j < 4; j++) {
                    FragB bf;
                    wmma::load_matrix_sync(bf, Ws + k0 * WSTR + wc * 64 + j * 16, WSTR);
                    cvt_tf32(bf);
                    wmma::mma_sync(acc[j], af, bf, acc[j]);
                }
            }
        }
    }

    // ---- phase 1 epilogue: acc -> Hs, bias+relu (smem only) ----
    __syncthreads();
#pragma unroll
    for (int j = 0; j < 4; j++)
        wmma::store_matrix_sync(Hs + wr * 16 * ASTR + wc * 64 + j * 16, acc[j],
                                ASTR, wmma::mem_row_major);
    __syncthreads();
    for (int i = tid; i < 2048; i += 256) {
        int r = i >> 5, c4 = i & 31;
        float4 v = *reinterpret_cast<float4*>(Hs + r * ASTR + c4 * 4);
        float4 bb = reinterpret_cast<const float4*>(b1)[c4];
        v.x = fmaxf(v.x + bb.x, 0.f);
        v.y = fmaxf(v.y + bb.y, 0.f);
        v.z = fmaxf(v.z + bb.z, 0.f);
        v.w = fmaxf(v.w + bb.w, 0.f);
        *reinterpret_cast<float4*>(Hs + r * ASTR + c4 * 4) = v;
    }

    // ---- phase 2: t2 = Hs @ W2l ; o_part = Hs @ W2r (shared Hs reads) ----
    const int r2 = wid >> 1;
    const int cb = (wid & 1) * 2;
    FragC a2f[2], a3f[2];
    wmma::fill_fragment(a2f[0], 0.0f);
    wmma::fill_fragment(a2f[1], 0.0f);
    wmma::fill_fragment(a3f[0], 0.0f);
    wmma::fill_fragment(a3f[1], 0.0f);

    for (int ck = 0; ck < 8; ck++) {
        __syncthreads();
        {
            int row = tid >> 4, c4 = tid & 15;
            *reinterpret_cast<float4*>(W2s + row * W2STR + c4 * 4) =
                reinterpret_cast<const float4*>(W2l)[(ck * 16 + row) * 16 + c4];
            *reinterpret_cast<float4*>(W3s + row * W2STR + c4 * 4) =
                reinterpret_cast<const float4*>(W2r)[(ck * 16 + row) * 16 + c4];
        }
        __syncthreads();
#pragma unroll
        for (int k0 = 0; k0 < 16; k0 += 8) {
            FragA af;
            wmma::load_matrix_sync(af, Hs + r2 * 16 * ASTR + ck * 16 + k0, ASTR);
            cvt_tf32(af);
#pragma unroll
            for (int j = 0; j < 2; j++) {
                FragB bf;
                wmma::load_matrix_sync(bf, W2s + k0 * W2STR + (cb + j) * 16, W2STR);
                cvt_tf32(bf);
                wmma::mma_sync(a2f[j], af, bf, a2f[j]);
                FragB bf2;
                wmma::load_matrix_sync(bf2, W3s + k0 * W2STR + (cb + j) * 16, W2STR);
                cvt_tf32(bf2);
                wmma::mma_sync(a3f[j], af, bf2, a3f[j]);
            }
        }
    }
#pragma unroll
    for (int j = 0; j < 2; j++) {
        wmma::store_matrix_sync(g_t2 + (size_t)(base + r2 * 16) * 64 + (cb + j) * 16,
                                a2f[j], 64, wmma::mem_row_major);   // padded
        wmma::store_matrix_sync(g_opart + (size_t)(base + r2 * 16) * 64 + (cb + j) * 16,
                                a3f[j], 64, wmma::mem_row_major);   // padded
    }
}

// ---------------- final kernel: out = mean-gather(t2) + o_part + b2 ------------
// (MLP=4 kept here: tiny register footprint, latency-bound gather)
__global__ void __launch_bounds__(256)
out_gather_kernel(const float* __restrict__ b2, float* __restrict__ outp, int N) {
    int node = (int)(((size_t)blockIdx.x * blockDim.x + threadIdx.x) >> 5);
    int lane = threadIdx.x & 31;
    if (node >= N) return;
    int beg = g_rowptr[node];
    int deg = g_cnt[node];
    int end = beg + deg;
    float2 a0 = make_float2(0.f, 0.f);
    float2 a1 = make_float2(0.f, 0.f);
    float2 a2 = make_float2(0.f, 0.f);
    float2 a3 = make_float2(0.f, 0.f);
    int i = beg;
    for (; i + 3 < end; i += 4) {
        int s0 = g_csr[i];
        int s1 = g_csr[i + 1];
        int s2 = g_csr[i + 2];
        int s3 = g_csr[i + 3];
        float2 v0 = reinterpret_cast<const float2*>(g_t2 + (size_t)s0 * 64)[lane];
        float2 v1 = reinterpret_cast<const float2*>(g_t2 + (size_t)s1 * 64)[lane];
        float2 v2 = reinterpret_cast<const float2*>(g_t2 + (size_t)s2 * 64)[lane];
        float2 v3 = reinterpret_cast<const float2*>(g_t2 + (size_t)s3 * 64)[lane];
        a0.x += v0.x; a0.y += v0.y;
        a1.x += v1.x; a1.y += v1.y;
        a2.x += v2.x; a2.y += v2.y;
        a3.x += v3.x; a3.y += v3.y;
    }
    for (; i < end; i++) {
        int s0 = g_csr[i];
        float2 v0 = reinterpret_cast<const float2*>(g_t2 + (size_t)s0 * 64)[lane];
        a0.x += v0.x; a0.y += v0.y;
    }
    float rd = (deg > 0) ? (1.0f / (float)deg) : 0.0f;
    float2 op = reinterpret_cast<const float2*>(g_opart + (size_t)node * 64)[lane];
    float2 bb = reinterpret_cast<const float2*>(b2)[lane];
    float2 r;
    r.x = (a0.x + a1.x + a2.x + a3.x) * rd + op.x + bb.x;
    r.y = (a0.y + a1.y + a2.y + a3.y) * rd + op.y + bb.y;
    reinterpret_cast<float2*>(outp + (size_t)node * 64)[lane] = r;
}

// ---------------- launch -------------------------------------------------------
extern "C" void kernel_launch(void* const* d_in, const int* in_sizes, int n_in,
                              void* d_out, int out_size) {
    const float* x       = (const float*)d_in[0];
    const int*   ei_w    = (const int*)d_in[1];
    const float* W1l     = (const float*)d_in[2];
    const float* b1      = (const float*)d_in[3];
    const float* W1r     = (const float*)d_in[4];
    const float* W2l     = (const float*)d_in[5];
    const float* b2      = (const float*)d_in[6];
    const float* W2r     = (const float*)d_in[7];
    float* out = (float*)d_out;

    int N = in_sizes[0] / 128;
    int E = in_sizes[1] / 2;
    int nblk = (N + SCAN_BLK - 1) / SCAN_BLK;

    // --- decode + CSR build (4 launches) ---
    detect_zero_kernel<<<nblk + 1, 256>>>(ei_w, N, nblk);
    convert_hist_kernel<<<(E + 255) / 256, 256>>>(ei_w, E, N);
    scan_atomic_kernel<<<nblk, SCAN_BLK>>>(N);
    fill_kernel<<<(E + 255) / 256, 256>>>(E);

    // --- layer 1 gather + dual GEMM + both layer-2 transforms ---
    gemm1_mega<<<(N + 63) / 64, 256>>>(x, W1l, W1r, b1, W2l, W2r, N);

    // --- final: gather t2-mean + add o_part + bias ---
    {
        size_t threads = (size_t)N * 32;
        out_gather_kernel<<<(int)((threads + 255) / 256), 256>>>(b2, out, N);
    }
}